// round 8
// baseline (speedup 1.0000x reference)
#include <cuda_runtime.h>
#include <cuda_bf16.h>
#include <math.h>
#include <stdint.h>

#define B_   8
#define S_   1024
#define D_   1152
#define H_   16
#define HD_  72
#define M_   (B_*S_)          // 8192
#define N3_  (3*D_)           // 3456
#define BHSHD (B_*H_*S_*HD_)  // 9437184
#define SCL 0.170044411294f   // 72^-0.5 * log2(e)

// Scratch (device globals; no allocations allowed)
__device__ float g_qkv[3u*BHSHD];                         // fp32 [3][B][H][S][HD]
__device__ __nv_bfloat16 g_qkvh[3u*BHSHD], g_qkvl[3u*BHSHD];
__device__ __nv_bfloat16 g_attnh[(size_t)M_*D_], g_attnl[(size_t)M_*D_];
__device__ __nv_bfloat16 g_hidh[(size_t)M_*D_],  g_hidl[(size_t)M_*D_];
__device__ __nv_bfloat16 g_wqh[(size_t)N3_*D_],  g_wql[(size_t)N3_*D_];
__device__ __nv_bfloat16 g_wph[(size_t)D_*D_],   g_wpl[(size_t)D_*D_];

// ---------------------------------------------------------------------------
// helpers
// ---------------------------------------------------------------------------
__device__ __forceinline__ uint32_t pk(__nv_bfloat16 a, __nv_bfloat16 b) {
    return (uint32_t)__bfloat16_as_ushort(a) | ((uint32_t)__bfloat16_as_ushort(b) << 16);
}
__device__ __forceinline__ void cvt_hi_lo(float4 v, uint2& hi, uint2& lo) {
    __nv_bfloat16 hx = __float2bfloat16(v.x), hy = __float2bfloat16(v.y);
    __nv_bfloat16 hz = __float2bfloat16(v.z), hw = __float2bfloat16(v.w);
    __nv_bfloat16 lx = __float2bfloat16(v.x - __bfloat162float(hx));
    __nv_bfloat16 ly = __float2bfloat16(v.y - __bfloat162float(hy));
    __nv_bfloat16 lz = __float2bfloat16(v.z - __bfloat162float(hz));
    __nv_bfloat16 lw = __float2bfloat16(v.w - __bfloat162float(hw));
    hi.x = pk(hx, hy); hi.y = pk(hz, hw);
    lo.x = pk(lx, ly); lo.y = pk(lz, lw);
}
__device__ __forceinline__ void mma16816(float* c, const uint32_t* a, const uint32_t* b) {
    asm volatile(
        "mma.sync.aligned.m16n8k16.row.col.f32.bf16.bf16.f32 "
        "{%0,%1,%2,%3}, {%4,%5,%6,%7}, {%8,%9}, {%0,%1,%2,%3};"
        : "+f"(c[0]), "+f"(c[1]), "+f"(c[2]), "+f"(c[3])
        : "r"(a[0]), "r"(a[1]), "r"(a[2]), "r"(a[3]), "r"(b[0]), "r"(b[1]));
}
__device__ __forceinline__ void ldm4(uint32_t* r, uint32_t a) {
    asm volatile("ldmatrix.sync.aligned.m8n8.x4.shared.b16 {%0,%1,%2,%3}, [%4];"
        : "=r"(r[0]), "=r"(r[1]), "=r"(r[2]), "=r"(r[3]) : "r"(a));
}
__device__ __forceinline__ void ldm4t(uint32_t* r, uint32_t a) {
    asm volatile("ldmatrix.sync.aligned.m8n8.x4.trans.shared.b16 {%0,%1,%2,%3}, [%4];"
        : "=r"(r[0]), "=r"(r[1]), "=r"(r[2]), "=r"(r[3]) : "r"(a));
}
__device__ __forceinline__ void ldm2t(uint32_t* r, uint32_t a) {
    asm volatile("ldmatrix.sync.aligned.m8n8.x2.trans.shared.b16 {%0,%1}, [%2];"
        : "=r"(r[0]), "=r"(r[1]) : "r"(a));
}
__device__ __forceinline__ void cp16(uint32_t dst, const void* src) {
    asm volatile("cp.async.cg.shared.global [%0], [%1], 16;" :: "r"(dst), "l"(src));
}
#define CP_COMMIT() asm volatile("cp.async.commit_group;")
template <int N> __device__ __forceinline__ void cp_wait() {
    asm volatile("cp.async.wait_group %0;" :: "n"(N));
}
// FMA-pipe 2^x for x <= 0 (no MUFU)
__device__ __forceinline__ float exp2p(float d) {
    d = fmaxf(d, -100.f);
    const float MAGIC = 12582912.f;
    float frnd = d + MAGIC;
    int   i    = __float_as_int(frnd) - __float_as_int(MAGIC);
    float f    = d - (frnd - MAGIC);
    float y = 9.6181e-3f;
    y = fmaf(y, f, 5.54906e-2f);
    y = fmaf(y, f, 2.402265e-1f);
    y = fmaf(y, f, 6.931472e-1f);
    y = fmaf(y, f, 1.f);
    return __int_as_float(__float_as_int(y) + (i << 23));
}

// ---------------------------------------------------------------------------
// fp32 -> hi/lo bf16 converters
// ---------------------------------------------------------------------------
template <int WHICH>
__global__ void cvt_pair(const float* __restrict__ src, int n4)
{
    int i = blockIdx.x * blockDim.x + threadIdx.x;
    if (i >= n4) return;
    __nv_bfloat16* h = (WHICH == 0) ? g_hidh : (WHICH == 1) ? g_wqh : g_wph;
    __nv_bfloat16* l = (WHICH == 0) ? g_hidl : (WHICH == 1) ? g_wql : g_wpl;
    float4 v = ((const float4*)src)[i];
    uint2 hi, lo; cvt_hi_lo(v, hi, lo);
    ((uint2*)h)[i] = hi;
    ((uint2*)l)[i] = lo;
}

// ---------------------------------------------------------------------------
// bf16 HMMA GEMM: 3-stage cp.async ring, ONE __syncthreads per K-chunk.
// BM=BN=128, BK=32, 256 thr. MODE 1: hidden x qkv_w -> scatter g_qkv.
// MODE 0: attn x proj_w -> C. Stage: Ah|Al|Bh|Bl, 128 x 40 bf16 each.
// ---------------------------------------------------------------------------
#define STG 40960          // bytes per stage
#define GSMEM (3*STG)      // 122880

template <int MODE>
__global__ __launch_bounds__(256)
void gemm_bf16(const float* __restrict__ bias, float* __restrict__ C, int N)
{
    extern __shared__ __nv_bfloat16 dsm[];
    const uint32_t sb = (uint32_t)__cvta_generic_to_shared(dsm);
    const int tid = threadIdx.x, wid = tid >> 5, lane = tid & 31;
    const int bm0 = blockIdx.y * 128, bn0 = blockIdx.x * 128;
    const int wm = (wid >> 2) * 64, wn = (wid & 3) * 32;
    const int K = D_;

    const __nv_bfloat16* Ah_ = MODE ? g_hidh : g_attnh;
    const __nv_bfloat16* Al_ = MODE ? g_hidl : g_attnl;
    const __nv_bfloat16* Bh_ = MODE ? g_wqh  : g_wph;
    const __nv_bfloat16* Bl_ = MODE ? g_wql  : g_wpl;

    float acc[4][4][4];
#pragma unroll
    for (int mt = 0; mt < 4; mt++)
#pragma unroll
        for (int nt = 0; nt < 4; nt++)
#pragma unroll
            for (int r = 0; r < 4; r++) acc[mt][nt][r] = 0.f;

    const int r0 = tid >> 2, r1 = (tid + 256) >> 2;
    const int kof0 = (tid & 3) * 8;

    auto issue = [&](int c, int s) {
        const uint32_t stb = sb + s * STG;
        const int k0 = c * 32;
        cp16(stb +         r0 * 80 + kof0 * 2, Ah_ + (size_t)(bm0 + r0) * K + k0 + kof0);
        cp16(stb +         r1 * 80 + kof0 * 2, Ah_ + (size_t)(bm0 + r1) * K + k0 + kof0);
        cp16(stb + 10240 + r0 * 80 + kof0 * 2, Al_ + (size_t)(bm0 + r0) * K + k0 + kof0);
        cp16(stb + 10240 + r1 * 80 + kof0 * 2, Al_ + (size_t)(bm0 + r1) * K + k0 + kof0);
        cp16(stb + 20480 + r0 * 80 + kof0 * 2, Bh_ + (size_t)(bn0 + r0) * K + k0 + kof0);
        cp16(stb + 20480 + r1 * 80 + kof0 * 2, Bh_ + (size_t)(bn0 + r1) * K + k0 + kof0);
        cp16(stb + 30720 + r0 * 80 + kof0 * 2, Bl_ + (size_t)(bn0 + r0) * K + k0 + kof0);
        cp16(stb + 30720 + r1 * 80 + kof0 * 2, Bl_ + (size_t)(bn0 + r1) * K + k0 + kof0);
        CP_COMMIT();
    };

    const int NCH = K / 32;   // 36
    issue(0, 0);
    issue(1, 1);
    for (int c = 0; c < NCH; c++) {
        if (c + 2 < NCH) cp_wait<1>(); else cp_wait<0>();
        __syncthreads();
        if (c + 2 < NCH) issue(c + 2, (c + 2) % 3);
        const uint32_t stb = sb + (c % 3) * STG;
        const uint32_t abase = stb + ((wm + (lane & 15)) * 40 + ((lane >> 4) * 8)) * 2;
        const uint32_t bbase = stb + 20480 +
            ((wn + ((lane >> 4) * 8) + (lane & 7)) * 40 + (((lane >> 3) & 1) * 8)) * 2;
#pragma unroll
        for (int ks = 0; ks < 2; ks++) {
            uint32_t ah[4][4], al[4][4], bhf[8], blf[8];
#pragma unroll
            for (int mt = 0; mt < 4; mt++) {
                ldm4(ah[mt], abase + ks * 32 + mt * 1280);
                ldm4(al[mt], abase + ks * 32 + mt * 1280 + 10240);
            }
            ldm4(&bhf[0], bbase + ks * 32);
            ldm4(&bhf[4], bbase + ks * 32 + 1280);
            ldm4(&blf[0], bbase + ks * 32 + 10240);
            ldm4(&blf[4], bbase + ks * 32 + 10240 + 1280);
#pragma unroll
            for (int mt = 0; mt < 4; mt++)
#pragma unroll
                for (int nt = 0; nt < 4; nt++) {
                    mma16816(acc[mt][nt], ah[mt], &bhf[nt * 2]);
                    mma16816(acc[mt][nt], ah[mt], &blf[nt * 2]);
                    mma16816(acc[mt][nt], al[mt], &bhf[nt * 2]);
                }
        }
    }

    const int g = lane >> 2, tg = (lane & 3) * 2;
#pragma unroll
    for (int mt = 0; mt < 4; mt++) {
#pragma unroll
        for (int nt = 0; nt < 4; nt++) {
#pragma unroll
            for (int r = 0; r < 4; r++) {
                const int m = bm0 + wm + mt * 16 + g + (r >= 2 ? 8 : 0);
                const int n = bn0 + wn + nt * 8 + tg + (r & 1);
                const float v = acc[mt][nt][r] + bias[n];
                if (MODE == 0) {
                    C[(size_t)m * N + n] = v;
                } else {
                    const int b = m >> 10, s2 = m & 1023;
                    const int t = n / D_;
                    const int rr = n - t * D_;
                    const int h = rr / HD_;
                    const int hd = rr - h * HD_;
                    g_qkv[(((size_t)(t * B_ + b) * H_ + h) * S_ + s2) * HD_ + hd] = v;
                }
            }
        }
    }
}

// ---------------------------------------------------------------------------
// RoPE + convert: q (rope, scaled), k (rope), v (copy) -> hi/lo bf16
// ---------------------------------------------------------------------------
__global__ void rope_cvt(const float* __restrict__ cosp,
                         const float* __restrict__ sinp)
{
    const int total = 3 * B_ * H_ * S_ * 36;
    int idx = blockIdx.x * blockDim.x + threadIdx.x;
    if (idx >= total) return;
    const int i = idx % 36;
    const int row = idx / 36;
    const int s = row & (S_ - 1);
    const int t = row >> 17;
    const float* base = g_qkv + (size_t)row * HD_;
    float x1 = base[i], x2 = base[i + 36];
    float y1, y2;
    if (t < 2) {
        y1 = x1 * cosp[s * HD_ + i]      - x2 * sinp[s * HD_ + i];
        y2 = x2 * cosp[s * HD_ + i + 36] + x1 * sinp[s * HD_ + i + 36];
        if (t == 0) { y1 *= SCL; y2 *= SCL; }
    } else { y1 = x1; y2 = x2; }
    __nv_bfloat16 h1 = __float2bfloat16(y1);
    __nv_bfloat16 h2 = __float2bfloat16(y2);
    const size_t o1 = (size_t)row * HD_ + i, o2 = o1 + 36;
    g_qkvh[o1] = h1; g_qkvl[o1] = __float2bfloat16(y1 - __bfloat162float(h1));
    g_qkvh[o2] = h2; g_qkvl[o2] = __float2bfloat16(y2 - __bfloat162float(h2));
}

// ---------------------------------------------------------------------------
// HMMA flash attention v3: 3-stage cp.async KV ring, one barrier per chunk.
// Stage layout (bytes, rel. to stage base): Kh@0, Kl@11264, Vh@22528, Vl@33792
// Rows: 64 keys x 88 bf16 (176 B row stride; data 144 B; K pads zeroed once).
// ---------------------------------------------------------------------------
#define ASTG 45056            // bytes per KV stage
#define ASMEM (3*ASTG)        // 135168

__global__ __launch_bounds__(256)
void attn2()
{
    extern __shared__ __nv_bfloat16 asm_[];
    char* smc = (char*)asm_;
    const uint32_t sb = (uint32_t)__cvta_generic_to_shared(asm_);
    const int tid = threadIdx.x, w = tid >> 5, lane = tid & 31;
    const int g = lane >> 2, tg = (lane & 3) * 2;
    const int bh = blockIdx.x, q0 = blockIdx.y * 128;
    const int b = bh >> 4, h = bh & 15;

    const __nv_bfloat16* qh = g_qkvh;
    const __nv_bfloat16* ql = g_qkvl;
    const __nv_bfloat16* kh = g_qkvh + (size_t)BHSHD;
    const __nv_bfloat16* kl = g_qkvl + (size_t)BHSHD;
    const __nv_bfloat16* vh = g_qkvh + (size_t)2 * BHSHD;
    const __nv_bfloat16* vl = g_qkvl + (size_t)2 * BHSHD;

    // ---- stage Q into stage0 region (Qh@0, Ql@22528 bytes), 88-elem stride ----
    for (int i = tid; i < 128 * 18; i += 256) {
        const int row = i / 18, c4 = (i % 18) * 4;
        const size_t go = ((size_t)(bh << 10) + q0 + row) * HD_ + c4;
        *(uint2*)(smc + row * 176 + c4 * 2)         = *(const uint2*)&qh[go];
        *(uint2*)(smc + 22528 + row * 176 + c4 * 2) = *(const uint2*)&ql[go];
    }
    for (int i = tid; i < 1024; i += 256) {       // zero Q pad cols 72..79
        const int arr = i / 512, r2 = i % 512;
        *(uint32_t*)(smc + arr * 22528 + (r2 / 4) * 176 + 144 + (r2 % 4) * 4) = 0u;
    }
    __syncthreads();

    // ---- Q frags ----
    uint32_t qfh[5][4], qfl[5][4];
    const uint32_t qbase = sb + ((w * 16 + (lane & 15)) * 88 + ((lane >> 4) * 8)) * 2;
#pragma unroll
    for (int c = 0; c < 5; c++) {
        ldm4(qfh[c], qbase + c * 32);
        ldm4(qfl[c], qbase + c * 32 + 22528);
    }
    __syncthreads();

    // ---- zero K pad cols (72..79) in all 3 stages ----
    for (int i = tid; i < 1536; i += 256) {
        const int st = i / 512, rem = i % 512;
        const int arr = rem / 256, r2 = rem % 256;
        *(uint32_t*)(smc + st * ASTG + arr * 11264 + (r2 / 4) * 176 + 144 + (r2 % 4) * 4) = 0u;
    }

    auto issue_kv = [&](int cidx, int s) {
        const uint32_t stb = sb + s * ASTG;
        const int j0 = cidx * 64;
        for (int i = tid; i < 576; i += 256) {
            const int row = i / 9, chb = (i % 9) * 16;
            const size_t go = ((size_t)(bh << 10) + j0 + row) * HD_ + chb / 2;
            const uint32_t d = stb + row * 176 + chb;
            cp16(d,         kh + go);
            cp16(d + 11264, kl + go);
            cp16(d + 22528, vh + go);
            cp16(d + 33792, vl + go);
        }
        CP_COMMIT();
    };

    float o[9][4];
#pragma unroll
    for (int n = 0; n < 9; n++) { o[n][0] = 0.f; o[n][1] = 0.f; o[n][2] = 0.f; o[n][3] = 0.f; }
    float mr0 = -1e30f, mr1 = -1e30f, lr0 = 0.f, lr1 = 0.f;

    issue_kv(0, 0);
    issue_kv(1, 1);
    const int NKC = S_ / 64;   // 16
    for (int c = 0; c < NKC; c++) {
        if (c + 2 < NKC) cp_wait<1>(); else cp_wait<0>();
        __syncthreads();
        if (c + 2 < NKC) issue_kv(c + 2, (c + 2) % 3);
        const uint32_t stb = sb + (c % 3) * ASTG;

        // ---- S = Q.K^T ----
        float s[8][4];
#pragma unroll
        for (int n = 0; n < 8; n++) { s[n][0] = 0.f; s[n][1] = 0.f; s[n][2] = 0.f; s[n][3] = 0.f; }
        const uint32_t kb0 = stb + ((((lane >> 4) * 8) + (lane & 7)) * 88 + (((lane >> 3) & 1) * 8)) * 2;
#pragma unroll
        for (int cc = 0; cc < 5; cc++) {
#pragma unroll
            for (int ktp = 0; ktp < 4; ktp++) {
                uint32_t fh[4], fl[4];
                ldm4(fh, kb0 + cc * 32 + ktp * 2816);
                ldm4(fl, kb0 + cc * 32 + ktp * 2816 + 11264);
                mma16816(s[ktp * 2],     qfh[cc], &fh[0]);
                mma16816(s[ktp * 2],     qfh[cc], &fl[0]);
                mma16816(s[ktp * 2],     qfl[cc], &fh[0]);
                mma16816(s[ktp * 2 + 1], qfh[cc], &fh[2]);
                mma16816(s[ktp * 2 + 1], qfh[cc], &fl[2]);
                mma16816(s[ktp * 2 + 1], qfl[cc], &fh[2]);
            }
        }

        // ---- online softmax ----
        float mx0 = s[0][0], mx1 = s[0][2];
#pragma unroll
        for (int n = 0; n < 8; n++) {
            mx0 = fmaxf(mx0, fmaxf(s[n][0], s[n][1]));
            mx1 = fmaxf(mx1, fmaxf(s[n][2], s[n][3]));
        }
        mx0 = fmaxf(mx0, __shfl_xor_sync(0xffffffffu, mx0, 1));
        mx0 = fmaxf(mx0, __shfl_xor_sync(0xffffffffu, mx0, 2));
        mx1 = fmaxf(mx1, __shfl_xor_sync(0xffffffffu, mx1, 1));
        mx1 = fmaxf(mx1, __shfl_xor_sync(0xffffffffu, mx1, 2));
        const float mn0 = fmaxf(mr0, mx0), mn1 = fmaxf(mr1, mx1);
        const float f0 = exp2p(mr0 - mn0), f1 = exp2p(mr1 - mn1);
        mr0 = mn0; mr1 = mn1;
        float sum0 = 0.f, sum1 = 0.f;
#pragma unroll
        for (int n = 0; n < 8; n++) {
            s[n][0] = exp2p(s[n][0] - mn0);
            s[n][1] = exp2p(s[n][1] - mn0);
            s[n][2] = exp2p(s[n][2] - mn1);
            s[n][3] = exp2p(s[n][3] - mn1);
            sum0 += s[n][0] + s[n][1];
            sum1 += s[n][2] + s[n][3];
        }
        lr0 = lr0 * f0 + sum0;
        lr1 = lr1 * f1 + sum1;
#pragma unroll
        for (int n = 0; n < 9; n++) {
            o[n][0] *= f0; o[n][1] *= f0; o[n][2] *= f1; o[n][3] *= f1;
        }

        // ---- O += P.V ----
#pragma unroll
        for (int c2 = 0; c2 < 4; c2++) {
            __nv_bfloat16 h00 = __float2bfloat16(s[2*c2][0]);
            __nv_bfloat16 h01 = __float2bfloat16(s[2*c2][1]);
            __nv_bfloat16 h02 = __float2bfloat16(s[2*c2][2]);
            __nv_bfloat16 h03 = __float2bfloat16(s[2*c2][3]);
            __nv_bfloat16 h10 = __float2bfloat16(s[2*c2+1][0]);
            __nv_bfloat16 h11 = __float2bfloat16(s[2*c2+1][1]);
            __nv_bfloat16 h12 = __float2bfloat16(s[2*c2+1][2]);
            __nv_bfloat16 h13 = __float2bfloat16(s[2*c2+1][3]);
            uint32_t ph[4], pl[4];
            ph[0] = pk(h00, h01); ph[1] = pk(h02, h03);
            ph[2] = pk(h10, h11); ph[3] = pk(h12, h13);
            pl[0] = pk(__float2bfloat16(s[2*c2][0]   - __bfloat162float(h00)),
                       __float2bfloat16(s[2*c2][1]   - __bfloat162float(h01)));
            pl[1] = pk(__float2bfloat16(s[2*c2][2]   - __bfloat162float(h02)),
                       __float2bfloat16(s[2*c2][3]   - __bfloat162float(h03)));
            pl[2] = pk(__float2bfloat16(s[2*c2+1][0] - __bfloat162float(h10)),
                       __float2bfloat16(s[2*c2+1][1] - __bfloat162float(h11)));
            pl[3] = pk(__float2bfloat16(s[2*c2+1][2] - __bfloat162float(h12)),
                       __float2bfloat16(s[2*c2+1][3] - __bfloat162float(h13)));

            const uint32_t vrow = stb + 22528 +
                ((c2 * 16 + ((lane >> 3) & 1) * 8 + (lane & 7)) * 88) * 2;
#pragma unroll
            for (int ntp = 0; ntp < 4; ntp++) {
                uint32_t fh[4], fl[4];
                ldm4t(fh, vrow + (2 * ntp + (lane >> 4)) * 16);
                ldm4t(fl, vrow + (2 * ntp + (lane >> 4)) * 16 + 11264);
                mma16816(o[2*ntp],     ph, &fh[0]);
                mma16816(o[2*ntp],     pl, &fh[0]);
                mma16816(o[2*ntp],     ph, &fl[0]);
                mma16816(o[2*ntp + 1], ph, &fh[2]);
                mma16816(o[2*ntp + 1], pl, &fh[2]);
                mma16816(o[2*ntp + 1], ph, &fl[2]);
            }
            uint32_t fh2[2], fl2[2];
            ldm2t(fh2, vrow + 128);
            ldm2t(fl2, vrow + 128 + 11264);
            mma16816(o[8], ph, fh2);
            mma16816(o[8], pl, fh2);
            mma16816(o[8], ph, fl2);
        }
    }

    // ---- finalize ----
    lr0 += __shfl_xor_sync(0xffffffffu, lr0, 1);
    lr0 += __shfl_xor_sync(0xffffffffu, lr0, 2);
    lr1 += __shfl_xor_sync(0xffffffffu, lr1, 1);
    lr1 += __shfl_xor_sync(0xffffffffu, lr1, 2);
    const float inv0 = 1.f / lr0, inv1 = 1.f / lr1;
    const int row0 = q0 + w * 16 + g;
    const size_t base0 = ((size_t)((b << 10) + row0) * D_ + h * HD_);
    const size_t base1 = base0 + (size_t)8 * D_;
#pragma unroll
    for (int n = 0; n < 9; n++) {
        float v00 = o[n][0] * inv0, v01 = o[n][1] * inv0;
        float v10 = o[n][2] * inv1, v11 = o[n][3] * inv1;
        __nv_bfloat16 a00 = __float2bfloat16(v00), a01 = __float2bfloat16(v01);
        __nv_bfloat16 a10 = __float2bfloat16(v10), a11 = __float2bfloat16(v11);
        g_attnh[base0 + n * 8 + tg]     = a00;
        g_attnh[base0 + n * 8 + tg + 1] = a01;
        g_attnh[base1 + n * 8 + tg]     = a10;
        g_attnh[base1 + n * 8 + tg + 1] = a11;
        g_attnl[base0 + n * 8 + tg]     = __float2bfloat16(v00 - __bfloat162float(a00));
        g_attnl[base0 + n * 8 + tg + 1] = __float2bfloat16(v01 - __bfloat162float(a01));
        g_attnl[base1 + n * 8 + tg]     = __float2bfloat16(v10 - __bfloat162float(a10));
        g_attnl[base1 + n * 8 + tg + 1] = __float2bfloat16(v11 - __bfloat162float(a11));
    }
}

// ---------------------------------------------------------------------------
// Launch
// ---------------------------------------------------------------------------
extern "C" void kernel_launch(void* const* d_in, const int* in_sizes, int n_in,
                              void* d_out, int out_size)
{
    const float* hidden = (const float*)d_in[0];
    const float* cosp   = (const float*)d_in[1];
    const float* sinp   = (const float*)d_in[2];
    const float* qkv_w  = (const float*)d_in[3];
    const float* qkv_b  = (const float*)d_in[4];
    const float* proj_w = (const float*)d_in[5];
    const float* proj_b = (const float*)d_in[6];
    float* out = (float*)d_out;

    cudaFuncSetAttribute(gemm_bf16<1>, cudaFuncAttributeMaxDynamicSharedMemorySize, GSMEM);
    cudaFuncSetAttribute(gemm_bf16<0>, cudaFuncAttributeMaxDynamicSharedMemorySize, GSMEM);
    cudaFuncSetAttribute(attn2, cudaFuncAttributeMaxDynamicSharedMemorySize, ASMEM);

    // 0) pre-convert inputs/weights to hi/lo bf16
    cvt_pair<0><<<(M_ * D_ / 4 + 255) / 256, 256>>>(hidden, M_ * D_ / 4);
    cvt_pair<1><<<(N3_ * D_ / 4 + 255) / 256, 256>>>(qkv_w, N3_ * D_ / 4);
    cvt_pair<2><<<(D_ * D_ / 4 + 255) / 256, 256>>>(proj_w, D_ * D_ / 4);

    // 1) QKV GEMM -> scatter fp32 g_qkv
    {
        dim3 grid(N3_ / 128, M_ / 128);
        gemm_bf16<1><<<grid, 256, GSMEM>>>(qkv_b, nullptr, N3_);
    }
    // 2) RoPE + convert q,k,v to hi/lo bf16
    {
        const int total = 3 * B_ * H_ * S_ * 36;
        rope_cvt<<<(total + 255) / 256, 256>>>(cosp, sinp);
    }
    // 3) attention -> hi/lo bf16 g_attn
    {
        dim3 grid(B_ * H_, S_ / 128);
        attn2<<<grid, 256, ASMEM>>>();
    }
    // 4) output projection
    {
        dim3 grid(D_ / 128, M_ / 128);
        gemm_bf16<0><<<grid, 256, GSMEM>>>(proj_b, out, D_);
    }
}

// round 12
// speedup vs baseline: 1.3824x; 1.3824x over previous
#include <cuda_runtime.h>
#include <cuda_bf16.h>
#include <math.h>
#include <stdint.h>

#define B_   8
#define S_   1024
#define D_   1152
#define H_   16
#define HD_  72
#define M_   (B_*S_)          // 8192
#define N3_  (3*D_)           // 3456
#define BHSHD (B_*H_*S_*HD_)  // 9437184
#define SCL 0.170044411294f   // 72^-0.5 * log2(e)

// Scratch (device globals; no allocations allowed)
__device__ float g_qkv[3u*BHSHD];                         // fp32 [3][B][H][S][HD]
__device__ __nv_bfloat16 g_qkvh[3u*BHSHD], g_qkvl[3u*BHSHD];
__device__ __nv_bfloat16 g_attnh[(size_t)M_*D_], g_attnl[(size_t)M_*D_];
__device__ __nv_bfloat16 g_hidh[(size_t)M_*D_],  g_hidl[(size_t)M_*D_];
__device__ __nv_bfloat16 g_wqh[(size_t)N3_*D_],  g_wql[(size_t)N3_*D_];
__device__ __nv_bfloat16 g_wph[(size_t)D_*D_],   g_wpl[(size_t)D_*D_];

// ---------------------------------------------------------------------------
// helpers
// ---------------------------------------------------------------------------
__device__ __forceinline__ uint32_t pk(__nv_bfloat16 a, __nv_bfloat16 b) {
    return (uint32_t)__bfloat16_as_ushort(a) | ((uint32_t)__bfloat16_as_ushort(b) << 16);
}
__device__ __forceinline__ void cvt_hi_lo(float4 v, uint2& hi, uint2& lo) {
    __nv_bfloat16 hx = __float2bfloat16(v.x), hy = __float2bfloat16(v.y);
    __nv_bfloat16 hz = __float2bfloat16(v.z), hw = __float2bfloat16(v.w);
    __nv_bfloat16 lx = __float2bfloat16(v.x - __bfloat162float(hx));
    __nv_bfloat16 ly = __float2bfloat16(v.y - __bfloat162float(hy));
    __nv_bfloat16 lz = __float2bfloat16(v.z - __bfloat162float(hz));
    __nv_bfloat16 lw = __float2bfloat16(v.w - __bfloat162float(hw));
    hi.x = pk(hx, hy); hi.y = pk(hz, hw);
    lo.x = pk(lx, ly); lo.y = pk(lz, lw);
}
__device__ __forceinline__ void mma16816(float* c, const uint32_t* a, const uint32_t* b) {
    asm volatile(
        "mma.sync.aligned.m16n8k16.row.col.f32.bf16.bf16.f32 "
        "{%0,%1,%2,%3}, {%4,%5,%6,%7}, {%8,%9}, {%0,%1,%2,%3};"
        : "+f"(c[0]), "+f"(c[1]), "+f"(c[2]), "+f"(c[3])
        : "r"(a[0]), "r"(a[1]), "r"(a[2]), "r"(a[3]), "r"(b[0]), "r"(b[1]));
}
__device__ __forceinline__ void ldm4(uint32_t* r, uint32_t a) {
    asm volatile("ldmatrix.sync.aligned.m8n8.x4.shared.b16 {%0,%1,%2,%3}, [%4];"
        : "=r"(r[0]), "=r"(r[1]), "=r"(r[2]), "=r"(r[3]) : "r"(a));
}
__device__ __forceinline__ void ldm4t(uint32_t* r, uint32_t a) {
    asm volatile("ldmatrix.sync.aligned.m8n8.x4.trans.shared.b16 {%0,%1,%2,%3}, [%4];"
        : "=r"(r[0]), "=r"(r[1]), "=r"(r[2]), "=r"(r[3]) : "r"(a));
}
__device__ __forceinline__ void ldm2t(uint32_t* r, uint32_t a) {
    asm volatile("ldmatrix.sync.aligned.m8n8.x2.trans.shared.b16 {%0,%1}, [%2];"
        : "=r"(r[0]), "=r"(r[1]) : "r"(a));
}
__device__ __forceinline__ void cp16(uint32_t dst, const void* src) {
    asm volatile("cp.async.cg.shared.global [%0], [%1], 16;" :: "r"(dst), "l"(src));
}
#define CP_COMMIT() asm volatile("cp.async.commit_group;")
template <int N> __device__ __forceinline__ void cp_wait() {
    asm volatile("cp.async.wait_group %0;" :: "n"(N));
}
// FMA-pipe 2^x for x <= 0 (no MUFU)
__device__ __forceinline__ float exp2p(float d) {
    d = fmaxf(d, -100.f);
    const float MAGIC = 12582912.f;
    float frnd = d + MAGIC;
    int   i    = __float_as_int(frnd) - __float_as_int(MAGIC);
    float f    = d - (frnd - MAGIC);
    float y = 9.6181e-3f;
    y = fmaf(y, f, 5.54906e-2f);
    y = fmaf(y, f, 2.402265e-1f);
    y = fmaf(y, f, 6.931472e-1f);
    y = fmaf(y, f, 1.f);
    return __int_as_float(__float_as_int(y) + (i << 23));
}

// ---------------------------------------------------------------------------
// fp32 -> hi/lo bf16 converters
// ---------------------------------------------------------------------------
template <int WHICH>
__global__ void cvt_pair(const float* __restrict__ src, int n4)
{
    int i = blockIdx.x * blockDim.x + threadIdx.x;
    if (i >= n4) return;
    __nv_bfloat16* h = (WHICH == 0) ? g_hidh : (WHICH == 1) ? g_wqh : g_wph;
    __nv_bfloat16* l = (WHICH == 0) ? g_hidl : (WHICH == 1) ? g_wql : g_wpl;
    float4 v = ((const float4*)src)[i];
    uint2 hi, lo; cvt_hi_lo(v, hi, lo);
    ((uint2*)h)[i] = hi;
    ((uint2*)l)[i] = lo;
}

// ---------------------------------------------------------------------------
// bf16 HMMA GEMM: BM=256, BN=128, BK=32, 512 thr (16 warps, 4/SMSP).
// 2-stage cp.async ring, R7-style issue-before-wait, two barriers/chunk.
// Stage layout (bytes): Ah@0 (256x80), Al@20480, Bh@40960 (128x80), Bl@51200.
// A-frags loaded per-mt to keep regs <=128 (512 thr -> full RF).
// MODE 1: hidden x qkv_w -> scatter fp32 g_qkv.  MODE 0: attn x proj_w -> C.
// ---------------------------------------------------------------------------
#define GSTG 61440
#define GSMEM (2*GSTG)     // 122880

template <int MODE>
__global__ __launch_bounds__(512)
void gemm_bf16(const float* __restrict__ bias, float* __restrict__ C, int N)
{
    extern __shared__ __nv_bfloat16 dsm[];
    const uint32_t sb = (uint32_t)__cvta_generic_to_shared(dsm);
    const int tid = threadIdx.x, wid = tid >> 5, lane = tid & 31;
    const int bm0 = blockIdx.y * 256, bn0 = blockIdx.x * 128;
    const int wm = (wid >> 2) * 64, wn = (wid & 3) * 32;
    const int K = D_;

    const __nv_bfloat16* Ah_ = MODE ? g_hidh : g_attnh;
    const __nv_bfloat16* Al_ = MODE ? g_hidl : g_attnl;
    const __nv_bfloat16* Bh_ = MODE ? g_wqh  : g_wph;
    const __nv_bfloat16* Bl_ = MODE ? g_wql  : g_wpl;

    float acc[4][4][4];
#pragma unroll
    for (int mt = 0; mt < 4; mt++)
#pragma unroll
        for (int nt = 0; nt < 4; nt++)
#pragma unroll
            for (int r = 0; r < 4; r++) acc[mt][nt][r] = 0.f;

    const int rowL = tid >> 2;            // 0..127
    const int kof  = (tid & 3) * 8;       // 0,8,16,24 (bf16 elems)

    auto issue = [&](int c, int s) {
        const uint32_t stb = sb + s * GSTG;
        const int k0 = c * 32;
        cp16(stb +         rowL * 80 + kof * 2,         Ah_ + (size_t)(bm0 + rowL) * K + k0 + kof);
        cp16(stb +         (rowL + 128) * 80 + kof * 2, Ah_ + (size_t)(bm0 + rowL + 128) * K + k0 + kof);
        cp16(stb + 20480 + rowL * 80 + kof * 2,         Al_ + (size_t)(bm0 + rowL) * K + k0 + kof);
        cp16(stb + 20480 + (rowL + 128) * 80 + kof * 2, Al_ + (size_t)(bm0 + rowL + 128) * K + k0 + kof);
        cp16(stb + 40960 + rowL * 80 + kof * 2,         Bh_ + (size_t)(bn0 + rowL) * K + k0 + kof);
        cp16(stb + 51200 + rowL * 80 + kof * 2,         Bl_ + (size_t)(bn0 + rowL) * K + k0 + kof);
        CP_COMMIT();
    };

    const int NCH = K / 32;   // 36
    issue(0, 0);
    for (int c = 0; c < NCH; c++) {
        const int s = c & 1;
        if (c + 1 < NCH) { issue(c + 1, s ^ 1); cp_wait<1>(); }
        else             { cp_wait<0>(); }
        __syncthreads();
        const uint32_t stb = sb + s * GSTG;
        const uint32_t abase = stb + ((wm + (lane & 15)) * 40 + ((lane >> 4) * 8)) * 2;
        const uint32_t bbase = stb + 40960 +
            ((wn + ((lane >> 4) * 8) + (lane & 7)) * 40 + (((lane >> 3) & 1) * 8)) * 2;
#pragma unroll
        for (int ks = 0; ks < 2; ks++) {
            uint32_t bhf[8], blf[8];
            ldm4(&bhf[0], bbase + ks * 32);
            ldm4(&bhf[4], bbase + ks * 32 + 1280);
            ldm4(&blf[0], bbase + ks * 32 + 10240);
            ldm4(&blf[4], bbase + ks * 32 + 10240 + 1280);
#pragma unroll
            for (int mt = 0; mt < 4; mt++) {
                uint32_t ah[4], al[4];
                ldm4(ah, abase + ks * 32 + mt * 1280);
                ldm4(al, abase + ks * 32 + mt * 1280 + 20480);
#pragma unroll
                for (int nt = 0; nt < 4; nt++) {
                    mma16816(acc[mt][nt], ah, &bhf[nt * 2]);
                    mma16816(acc[mt][nt], ah, &blf[nt * 2]);
                    mma16816(acc[mt][nt], al, &bhf[nt * 2]);
                }
            }
        }
        __syncthreads();
    }

    const int g = lane >> 2, tg = (lane & 3) * 2;
#pragma unroll
    for (int mt = 0; mt < 4; mt++) {
#pragma unroll
        for (int nt = 0; nt < 4; nt++) {
#pragma unroll
            for (int r = 0; r < 4; r++) {
                const int m = bm0 + wm + mt * 16 + g + (r >= 2 ? 8 : 0);
                const int n = bn0 + wn + nt * 8 + tg + (r & 1);
                const float v = acc[mt][nt][r] + bias[n];
                if (MODE == 0) {
                    C[(size_t)m * N + n] = v;
                } else {
                    const int b = m >> 10, s2 = m & 1023;
                    const int t = n / D_;
                    const int rr = n - t * D_;
                    const int h = rr / HD_;
                    const int hd = rr - h * HD_;
                    g_qkv[(((size_t)(t * B_ + b) * H_ + h) * S_ + s2) * HD_ + hd] = v;
                }
            }
        }
    }
}

// ---------------------------------------------------------------------------
// RoPE + convert: q (rope, scaled), k (rope), v (copy) -> hi/lo bf16
// ---------------------------------------------------------------------------
__global__ void rope_cvt(const float* __restrict__ cosp,
                         const float* __restrict__ sinp)
{
    const int total = 3 * B_ * H_ * S_ * 36;
    int idx = blockIdx.x * blockDim.x + threadIdx.x;
    if (idx >= total) return;
    const int i = idx % 36;
    const int row = idx / 36;
    const int s = row & (S_ - 1);
    const int t = row >> 17;
    const float* base = g_qkv + (size_t)row * HD_;
    float x1 = base[i], x2 = base[i + 36];
    float y1, y2;
    if (t < 2) {
        y1 = x1 * cosp[s * HD_ + i]      - x2 * sinp[s * HD_ + i];
        y2 = x2 * cosp[s * HD_ + i + 36] + x1 * sinp[s * HD_ + i + 36];
        if (t == 0) { y1 *= SCL; y2 *= SCL; }
    } else { y1 = x1; y2 = x2; }
    __nv_bfloat16 h1 = __float2bfloat16(y1);
    __nv_bfloat16 h2 = __float2bfloat16(y2);
    const size_t o1 = (size_t)row * HD_ + i, o2 = o1 + 36;
    g_qkvh[o1] = h1; g_qkvl[o1] = __float2bfloat16(y1 - __bfloat162float(h1));
    g_qkvh[o2] = h2; g_qkvl[o2] = __float2bfloat16(y2 - __bfloat162float(h2));
}

// ---------------------------------------------------------------------------
// HMMA flash attention (exact R7 version, known-good at 1551 total):
// bf16 inputs, ldmatrix frags, ldmatrix.trans for V, two barriers per chunk.
// ---------------------------------------------------------------------------
__global__ __launch_bounds__(256)
void attn2()
{
    __shared__ __nv_bfloat16 sm[22528];
    const uint32_t sb = (uint32_t)__cvta_generic_to_shared(sm);
    const int tid = threadIdx.x, w = tid >> 5, lane = tid & 31;
    const int g = lane >> 2, tg = (lane & 3) * 2;
    const int bh = blockIdx.x, q0 = blockIdx.y * 128;
    const int b = bh >> 4, h = bh & 15;

    const __nv_bfloat16* qh = g_qkvh;
    const __nv_bfloat16* ql = g_qkvl;
    const __nv_bfloat16* kh = g_qkvh + (size_t)BHSHD;
    const __nv_bfloat16* kl = g_qkvl + (size_t)BHSHD;
    const __nv_bfloat16* vh = g_qkvh + (size_t)2 * BHSHD;
    const __nv_bfloat16* vl = g_qkvl + (size_t)2 * BHSHD;

    // ---- stage Q (already SCL-scaled) ----
    for (int i = tid; i < 128 * 18; i += 256) {
        const int row = i / 18, c4 = (i % 18) * 4;
        const size_t go = ((size_t)(bh << 10) + q0 + row) * HD_ + c4;
        *(uint2*)&sm[row * 88 + c4]         = *(const uint2*)&qh[go];
        *(uint2*)&sm[11264 + row * 88 + c4] = *(const uint2*)&ql[go];
    }
    for (int i = tid; i < 128 * 4; i += 256) {  // zero pad cols 72..79
        const int row = i >> 2, c = (i & 3) * 2;
        *(uint32_t*)&sm[row * 88 + 72 + c] = 0u;
        *(uint32_t*)&sm[11264 + row * 88 + 72 + c] = 0u;
    }
    __syncthreads();

    // ---- Q frags ----
    uint32_t qfh[5][4], qfl[5][4];
    const uint32_t qbase = sb + ((w * 16 + (lane & 15)) * 88 + ((lane >> 4) * 8)) * 2;
#pragma unroll
    for (int c = 0; c < 5; c++) {
        ldm4(qfh[c], qbase + c * 32);
        ldm4(qfl[c], qbase + c * 32 + 22528);
    }
    __syncthreads();

    // ---- zero K pad cols 72..79 (once; staging never writes them) ----
    for (int i = tid; i < 64 * 4; i += 256) {
        const int row = i >> 2, c = (i & 3) * 2;
        *(uint32_t*)&sm[row * 88 + 72 + c] = 0u;
        *(uint32_t*)&sm[5632 + row * 88 + 72 + c] = 0u;
    }

    float o[9][4];
#pragma unroll
    for (int n = 0; n < 9; n++) { o[n][0] = 0.f; o[n][1] = 0.f; o[n][2] = 0.f; o[n][3] = 0.f; }
    float mr0 = -1e30f, mr1 = -1e30f, lr0 = 0.f, lr1 = 0.f;

    for (int j0 = 0; j0 < S_; j0 += 64) {
        // ---- stage K and V (straight row copies, bf16) ----
        for (int i = tid; i < 64 * 18; i += 256) {
            const int row = i / 18, c4 = (i % 18) * 4;
            const size_t go = ((size_t)(bh << 10) + j0 + row) * HD_ + c4;
            *(uint2*)&sm[row * 88 + c4]         = *(const uint2*)&kh[go];
            *(uint2*)&sm[5632 + row * 88 + c4]  = *(const uint2*)&kl[go];
            *(uint2*)&sm[11264 + row * 88 + c4] = *(const uint2*)&vh[go];
            *(uint2*)&sm[16896 + row * 88 + c4] = *(const uint2*)&vl[go];
        }
        __syncthreads();

        // ---- S = Q.K^T ----
        float s[8][4];
#pragma unroll
        for (int n = 0; n < 8; n++) { s[n][0] = 0.f; s[n][1] = 0.f; s[n][2] = 0.f; s[n][3] = 0.f; }
        const uint32_t kb0 = sb + ((((lane >> 4) * 8) + (lane & 7)) * 88 + (((lane >> 3) & 1) * 8)) * 2;
#pragma unroll
        for (int c = 0; c < 5; c++) {
#pragma unroll
            for (int ktp = 0; ktp < 4; ktp++) {
                uint32_t fh[4], fl[4];
                ldm4(fh, kb0 + c * 32 + ktp * 2816);
                ldm4(fl, kb0 + c * 32 + ktp * 2816 + 11264);
                mma16816(s[ktp * 2],     qfh[c], &fh[0]);
                mma16816(s[ktp * 2],     qfh[c], &fl[0]);
                mma16816(s[ktp * 2],     qfl[c], &fh[0]);
                mma16816(s[ktp * 2 + 1], qfh[c], &fh[2]);
                mma16816(s[ktp * 2 + 1], qfh[c], &fl[2]);
                mma16816(s[ktp * 2 + 1], qfl[c], &fh[2]);
            }
        }

        // ---- online softmax (rows g, g+8) ----
        float mx0 = s[0][0], mx1 = s[0][2];
#pragma unroll
        for (int n = 0; n < 8; n++) {
            mx0 = fmaxf(mx0, fmaxf(s[n][0], s[n][1]));
            mx1 = fmaxf(mx1, fmaxf(s[n][2], s[n][3]));
        }
        mx0 = fmaxf(mx0, __shfl_xor_sync(0xffffffffu, mx0, 1));
        mx0 = fmaxf(mx0, __shfl_xor_sync(0xffffffffu, mx0, 2));
        mx1 = fmaxf(mx1, __shfl_xor_sync(0xffffffffu, mx1, 1));
        mx1 = fmaxf(mx1, __shfl_xor_sync(0xffffffffu, mx1, 2));
        const float mn0 = fmaxf(mr0, mx0), mn1 = fmaxf(mr1, mx1);
        const float f0 = exp2p(mr0 - mn0), f1 = exp2p(mr1 - mn1);
        mr0 = mn0; mr1 = mn1;
        float sum0 = 0.f, sum1 = 0.f;
#pragma unroll
        for (int n = 0; n < 8; n++) {
            s[n][0] = exp2p(s[n][0] - mn0);
            s[n][1] = exp2p(s[n][1] - mn0);
            s[n][2] = exp2p(s[n][2] - mn1);
            s[n][3] = exp2p(s[n][3] - mn1);
            sum0 += s[n][0] + s[n][1];
            sum1 += s[n][2] + s[n][3];
        }
        lr0 = lr0 * f0 + sum0;
        lr1 = lr1 * f1 + sum1;
#pragma unroll
        for (int n = 0; n < 9; n++) {
            o[n][0] *= f0; o[n][1] *= f0; o[n][2] *= f1; o[n][3] *= f1;
        }

        // ---- O += P.V  (V frags via ldmatrix.trans from [key][d] layout) ----
#pragma unroll
        for (int c2 = 0; c2 < 4; c2++) {
            __nv_bfloat16 h00 = __float2bfloat16(s[2*c2][0]);
            __nv_bfloat16 h01 = __float2bfloat16(s[2*c2][1]);
            __nv_bfloat16 h02 = __float2bfloat16(s[2*c2][2]);
            __nv_bfloat16 h03 = __float2bfloat16(s[2*c2][3]);
            __nv_bfloat16 h10 = __float2bfloat16(s[2*c2+1][0]);
            __nv_bfloat16 h11 = __float2bfloat16(s[2*c2+1][1]);
            __nv_bfloat16 h12 = __float2bfloat16(s[2*c2+1][2]);
            __nv_bfloat16 h13 = __float2bfloat16(s[2*c2+1][3]);
            uint32_t ph[4], pl[4];
            ph[0] = pk(h00, h01); ph[1] = pk(h02, h03);
            ph[2] = pk(h10, h11); ph[3] = pk(h12, h13);
            pl[0] = pk(__float2bfloat16(s[2*c2][0]   - __bfloat162float(h00)),
                       __float2bfloat16(s[2*c2][1]   - __bfloat162float(h01)));
            pl[1] = pk(__float2bfloat16(s[2*c2][2]   - __bfloat162float(h02)),
                       __float2bfloat16(s[2*c2][3]   - __bfloat162float(h03)));
            pl[2] = pk(__float2bfloat16(s[2*c2+1][0] - __bfloat162float(h10)),
                       __float2bfloat16(s[2*c2+1][1] - __bfloat162float(h11)));
            pl[3] = pk(__float2bfloat16(s[2*c2+1][2] - __bfloat162float(h12)),
                       __float2bfloat16(s[2*c2+1][3] - __bfloat162float(h13)));

            const uint32_t vrow = sb + 22528 +
                ((c2 * 16 + ((lane >> 3) & 1) * 8 + (lane & 7)) * 88) * 2;
#pragma unroll
            for (int ntp = 0; ntp < 4; ntp++) {
                uint32_t fh[4], fl[4];
                ldm4t(fh, vrow + (2 * ntp + (lane >> 4)) * 16);
                ldm4t(fl, vrow + (2 * ntp + (lane >> 4)) * 16 + 11264);
                mma16816(o[2*ntp],     ph, &fh[0]);
                mma16816(o[2*ntp],     pl, &fh[0]);
                mma16816(o[2*ntp],     ph, &fl[0]);
                mma16816(o[2*ntp + 1], ph, &fh[2]);
                mma16816(o[2*ntp + 1], pl, &fh[2]);
                mma16816(o[2*ntp + 1], ph, &fl[2]);
            }
            uint32_t fh2[2], fl2[2];
            ldm2t(fh2, vrow + 128);            // d cols 64..71
            ldm2t(fl2, vrow + 128 + 11264);
            mma16816(o[8], ph, fh2);
            mma16816(o[8], pl, fh2);
            mma16816(o[8], ph, fl2);
        }
        __syncthreads();
    }

    // ---- finalize ----
    lr0 += __shfl_xor_sync(0xffffffffu, lr0, 1);
    lr0 += __shfl_xor_sync(0xffffffffu, lr0, 2);
    lr1 += __shfl_xor_sync(0xffffffffu, lr1, 1);
    lr1 += __shfl_xor_sync(0xffffffffu, lr1, 2);
    const float inv0 = 1.f / lr0, inv1 = 1.f / lr1;
    const int row0 = q0 + w * 16 + g;
    const size_t base0 = ((size_t)((b << 10) + row0) * D_ + h * HD_);
    const size_t base1 = base0 + (size_t)8 * D_;
#pragma unroll
    for (int n = 0; n < 9; n++) {
        float v00 = o[n][0] * inv0, v01 = o[n][1] * inv0;
        float v10 = o[n][2] * inv1, v11 = o[n][3] * inv1;
        __nv_bfloat16 a00 = __float2bfloat16(v00), a01 = __float2bfloat16(v01);
        __nv_bfloat16 a10 = __float2bfloat16(v10), a11 = __float2bfloat16(v11);
        g_attnh[base0 + n * 8 + tg]     = a00;
        g_attnh[base0 + n * 8 + tg + 1] = a01;
        g_attnh[base1 + n * 8 + tg]     = a10;
        g_attnh[base1 + n * 8 + tg + 1] = a11;
        g_attnl[base0 + n * 8 + tg]     = __float2bfloat16(v00 - __bfloat162float(a00));
        g_attnl[base0 + n * 8 + tg + 1] = __float2bfloat16(v01 - __bfloat162float(a01));
        g_attnl[base1 + n * 8 + tg]     = __float2bfloat16(v10 - __bfloat162float(a10));
        g_attnl[base1 + n * 8 + tg + 1] = __float2bfloat16(v11 - __bfloat162float(a11));
    }
}

// ---------------------------------------------------------------------------
// Launch
// ---------------------------------------------------------------------------
extern "C" void kernel_launch(void* const* d_in, const int* in_sizes, int n_in,
                              void* d_out, int out_size)
{
    const float* hidden = (const float*)d_in[0];
    const float* cosp   = (const float*)d_in[1];
    const float* sinp   = (const float*)d_in[2];
    const float* qkv_w  = (const float*)d_in[3];
    const float* qkv_b  = (const float*)d_in[4];
    const float* proj_w = (const float*)d_in[5];
    const float* proj_b = (const float*)d_in[6];
    float* out = (float*)d_out;

    cudaFuncSetAttribute(gemm_bf16<1>, cudaFuncAttributeMaxDynamicSharedMemorySize, GSMEM);
    cudaFuncSetAttribute(gemm_bf16<0>, cudaFuncAttributeMaxDynamicSharedMemorySize, GSMEM);

    // 0) pre-convert inputs/weights to hi/lo bf16
    cvt_pair<0><<<(M_ * D_ / 4 + 255) / 256, 256>>>(hidden, M_ * D_ / 4);
    cvt_pair<1><<<(N3_ * D_ / 4 + 255) / 256, 256>>>(qkv_w, N3_ * D_ / 4);
    cvt_pair<2><<<(D_ * D_ / 4 + 255) / 256, 256>>>(proj_w, D_ * D_ / 4);

    // 1) QKV GEMM -> scatter fp32 g_qkv
    {
        dim3 grid(N3_ / 128, M_ / 256);
        gemm_bf16<1><<<grid, 512, GSMEM>>>(qkv_b, nullptr, N3_);
    }
    // 2) RoPE + convert q,k,v to hi/lo bf16
    {
        const int total = 3 * B_ * H_ * S_ * 36;
        rope_cvt<<<(total + 255) / 256, 256>>>(cosp, sinp);
    }
    // 3) attention -> hi/lo bf16 g_attn
    {
        dim3 grid(B_ * H_, S_ / 128);
        attn2<<<grid, 256>>>();
    }
    // 4) output projection
    {
        dim3 grid(D_ / 128, M_ / 256);
        gemm_bf16<0><<<grid, 512, GSMEM>>>(proj_b, out, D_);
    }
}